// round 14
// baseline (speedup 1.0000x reference)
#include <cuda_runtime.h>

#define NUM_EDGE_TYPES 38
#define NUM_NODE_TYPES 4
#define HIDDEN 64
#define N_NODES 100000
#define N_EDGES 1600000
#define NUM_COMBOS (NUM_EDGE_TYPES * NUM_NODE_TYPES * NUM_NODE_TYPES)  // 608
#define STRIDE 64                 // in-degree cap; Poisson(16) tail @64 ~ 1e-19
#define NTP_WORDS (N_NODES / 16)  // 2-bit packed node types (25 KB, L1-resident)
#define SRC_MASK 0x1FFFF          // src < 100000 < 2^17; combo in bits [17,27)

// Scratch (device globals — no allocation allowed).
__device__ float    g_lut[NUM_COMBOS];
__device__ unsigned g_ntp[NTP_WORDS];
__device__ int      g_cnt[N_NODES];
__device__ unsigned g_slot[STRIDE * N_NODES];  // in-CSR, column-major: [i*N + v] = src | combo<<17
__device__ float    g_S[N_NODES];              // aggr after hop 1
__device__ float    g_A2[N_NODES];             // aggr after hop 2
__device__ float    g_A3[N_NODES];             // aggr after hop 3

// Monotonic (replay-safe) grid barrier. Never reset.
__device__ unsigned g_arrive = 0;
__device__ volatile unsigned g_release = 0;

__device__ __forceinline__ void grid_barrier(unsigned nb) {
    __syncthreads();
    if (threadIdx.x == 0) {
        __threadfence();
        unsigned ticket = atomicAdd(&g_arrive, 1u);
        unsigned target = ticket - (ticket % nb) + nb;
        if (ticket % nb == nb - 1u) {
            g_release = target;
        } else {
            while (*(volatile unsigned*)&g_release < target) { }
        }
        __threadfence();
    }
    __syncthreads();
}

__device__ __forceinline__ int ntp_lookup(int id) {
    return (int)((__ldg(&g_ntp[id >> 4]) >> ((id & 15) << 1)) & 3u);
}

// ---------------------------------------------------------------------------
// Hop gather, 4 threads/node (phases 0..3), MLP-2 inner loop.
//   out[v] = S[v] + sum_{in-edges e of v} in[src_e]
// LIMP is padded to a multiple of NT: uniform trips -> full-mask shuffles legal.
// ---------------------------------------------------------------------------
__device__ __forceinline__ void hop4(const float* __restrict__ in,
                                     float* __restrict__ out,
                                     int gt, int NT, int LIMP) {
    for (int t = gt; t < LIMP; t += NT) {
        int v = t >> 2, ph = t & 3;
        float a0 = 0.f, a1 = 0.f;
        if (v < N_NODES) {
            int c = min(g_cnt[v], STRIDE);
            int i = ph;
            for (; i + 4 < c; i += 8) {
                unsigned s0 = g_slot[(i    ) * N_NODES + v];
                unsigned s1 = g_slot[(i + 4) * N_NODES + v];
                a0 += __ldg(in + (s0 & SRC_MASK));
                a1 += __ldg(in + (s1 & SRC_MASK));
            }
            if (i < c) a0 += __ldg(in + (g_slot[i * N_NODES + v] & SRC_MASK));
        }
        float sum = a0 + a1;
        sum += __shfl_xor_sync(0xffffffffu, sum, 1);
        sum += __shfl_xor_sync(0xffffffffu, sum, 2);
        if (ph == 0 && v < N_NODES) out[v] = g_S[v] + sum;
    }
}

// ---------------------------------------------------------------------------
// ONE persistent kernel: init -> build -> S-pass -> 3 hops (grid barriers).
// ---------------------------------------------------------------------------
__global__ void __launch_bounds__(256) gsc_all(
    const int* __restrict__ src, const int* __restrict__ dst,
    const int* __restrict__ etyp, const int* __restrict__ ntyp,
    const float* __restrict__ W1, const float* __restrict__ b1,
    const float* __restrict__ W2, const float* __restrict__ b2,
    float* __restrict__ out, unsigned NB, int NT, int LIMP) {
    __shared__ float lut_s[NUM_COMBOS];
    int gt = blockIdx.x * 256 + threadIdx.x;

    // ================= phase 0: LUT + pack node types + zero cursors =========
    if (gt < NUM_COMBOS * 32) {          // 32 lanes per combo, shuffle reduce
        int combo = gt >> 5, lane = gt & 31;
        int et = combo >> 4, ht = (combo >> 2) & 3, tt = combo & 3;
        float acc = 0.f;
#pragma unroll
        for (int j = 0; j < 2; j++) {
            int k = lane + j * 32;
            float h = W1[et * HIDDEN + k]
                    + W1[(NUM_EDGE_TYPES + ht) * HIDDEN + k]
                    + W1[(NUM_EDGE_TYPES + NUM_NODE_TYPES + tt) * HIDDEN + k]
                    + b1[k];
            float h3 = h * h * h;        // jax.nn.gelu default (tanh approximation)
            float g = 0.5f * h * (1.f + tanhf(0.7978845608028654f * (h + 0.044715f * h3)));
            acc = fmaf(g, W2[k], acc);
        }
#pragma unroll
        for (int o = 16; o > 0; o >>= 1) acc += __shfl_xor_sync(0xffffffffu, acc, o);
        if (lane == 0) g_lut[combo] = 1.f / (1.f + expf(-(acc + b2[0])));
    }

    for (int w = gt; w < NTP_WORDS; w += NT) {
        const int* nt4 = ntyp + (w << 4);
        unsigned p = 0;
#pragma unroll
        for (int j = 0; j < 4; j++) {
            int4 q = *reinterpret_cast<const int4*>(nt4 + j * 4);
            p |= (unsigned)(q.x & 3) << ((j * 4 + 0) << 1);
            p |= (unsigned)(q.y & 3) << ((j * 4 + 1) << 1);
            p |= (unsigned)(q.z & 3) << ((j * 4 + 2) << 1);
            p |= (unsigned)(q.w & 3) << ((j * 4 + 3) << 1);
        }
        g_ntp[w] = p;
    }

    for (int v = gt; v < N_NODES; v += NT) g_cnt[v] = 0;
    grid_barrier(NB);

    // ================= phase 1: build packed in-CSR ==========================
    // 2 random ops/edge: cursor ATOMG + scattered 4B slot store.
    for (int i = gt * 4; i < N_EDGES; i += NT * 4) {
        int4 s = *reinterpret_cast<const int4*>(src + i);
        int4 d = *reinterpret_cast<const int4*>(dst + i);
        int4 t = *reinterpret_cast<const int4*>(etyp + i);

        unsigned c0 = (unsigned)((t.x << 4) + (ntp_lookup(s.x) << 2) + ntp_lookup(d.x));
        unsigned c1 = (unsigned)((t.y << 4) + (ntp_lookup(s.y) << 2) + ntp_lookup(d.y));
        unsigned c2 = (unsigned)((t.z << 4) + (ntp_lookup(s.z) << 2) + ntp_lookup(d.z));
        unsigned c3 = (unsigned)((t.w << 4) + (ntp_lookup(s.w) << 2) + ntp_lookup(d.w));

        int p0 = atomicAdd(&g_cnt[d.x], 1);
        int p1 = atomicAdd(&g_cnt[d.y], 1);
        int p2 = atomicAdd(&g_cnt[d.z], 1);
        int p3 = atomicAdd(&g_cnt[d.w], 1);

        if (p0 < STRIDE) g_slot[p0 * N_NODES + d.x] = (unsigned)s.x | (c0 << 17);
        if (p1 < STRIDE) g_slot[p1 * N_NODES + d.y] = (unsigned)s.y | (c1 << 17);
        if (p2 < STRIDE) g_slot[p2 * N_NODES + d.z] = (unsigned)s.z | (c2 << 17);
        if (p3 < STRIDE) g_slot[p3 * N_NODES + d.w] = (unsigned)s.w | (c3 << 17);
    }

    // LUT -> smem for the S-pass (g_lut final since the phase-0 barrier).
    for (int k = threadIdx.x; k < NUM_COMBOS; k += 256) lut_s[k] = g_lut[k];
    grid_barrier(NB);

    // ================= phase 2: S-pass (aggr after hop 1) ====================
    for (int t = gt; t < LIMP; t += NT) {
        int v = t >> 2, ph = t & 3;
        float a0 = 0.f, a1 = 0.f;
        if (v < N_NODES) {
            int c = min(g_cnt[v], STRIDE);
            int i = ph;
            for (; i + 4 < c; i += 8) {
                unsigned s0 = g_slot[(i    ) * N_NODES + v];
                unsigned s1 = g_slot[(i + 4) * N_NODES + v];
                a0 += lut_s[s0 >> 17];
                a1 += lut_s[s1 >> 17];
            }
            if (i < c) a0 += lut_s[g_slot[i * N_NODES + v] >> 17];
        }
        float sum = a0 + a1;
        sum += __shfl_xor_sync(0xffffffffu, sum, 1);
        sum += __shfl_xor_sync(0xffffffffu, sum, 2);
        if (ph == 0 && v < N_NODES) g_S[v] = sum;
    }
    grid_barrier(NB);

    // ================= phases 3..5: gather hops ==============================
    hop4(g_S, g_A2, gt, NT, LIMP);    // hop 2
    grid_barrier(NB);
    hop4(g_A2, g_A3, gt, NT, LIMP);   // hop 3
    grid_barrier(NB);
    hop4(g_A3, out, gt, NT, LIMP);    // hop 4 -> d_out
}

extern "C" void kernel_launch(void* const* d_in, const int* in_sizes, int n_in,
                              void* d_out, int out_size) {
    const int* edge_index = (const int*)d_in[0];   // [2, E]
    const int* edge_type  = (const int*)d_in[1];   // [E]
    const int* node_type  = (const int*)d_in[2];   // [N]
    const float* W1 = (const float*)d_in[3];
    const float* b1 = (const float*)d_in[4];
    const float* W2 = (const float*)d_in[5];
    const float* b2 = (const float*)d_in[6];
    float* out = (float*)d_out;                    // [N, 1]

    const int* src = edge_index;
    const int* dst = edge_index + N_EDGES;

    int dev = 0, sm = 148;
    cudaGetDevice(&dev);
    cudaDeviceGetAttribute(&sm, cudaDevAttrMultiProcessorCount, dev);

    // Residency-safe grid for the barrier: actual occupancy of THIS kernel.
    int occ = 0;
    cudaOccupancyMaxActiveBlocksPerMultiprocessor(&occ, gsc_all, 256, 0);
    if (occ < 1) occ = 1;
    if (occ > 8) occ = 8;
    unsigned NB = (unsigned)(sm * occ);
    int NT = (int)NB * 256;
    int LIMP = ((4 * N_NODES + NT - 1) / NT) * NT;  // padded: uniform warp trips

    gsc_all<<<NB, 256>>>(src, dst, edge_type, node_type,
                         W1, b1, W2, b2, out, NB, NT, LIMP);
}

// round 15
// speedup vs baseline: 1.4600x; 1.4600x over previous
#include <cuda_runtime.h>

#define NUM_EDGE_TYPES 38
#define NUM_NODE_TYPES 4
#define HIDDEN 64
#define N_NODES 100000
#define N_EDGES 1600000
#define NUM_COMBOS (NUM_EDGE_TYPES * NUM_NODE_TYPES * NUM_NODE_TYPES)  // 608
#define STRIDE 64                 // in-degree cap; Poisson(16) tail @64 ~ 1e-19
#define NTP_WORDS (N_NODES / 16)  // 2-bit packed node types (25 KB, L1-resident)
#define SRC_MASK 0x1FFFF          // src < 100000 < 2^17; combo in bits [17,27)

// Scratch (device globals — no allocation allowed).
__device__ float    g_lut[NUM_COMBOS];
__device__ unsigned g_ntp[NTP_WORDS];
__device__ int      g_cnt[N_NODES];
__device__ unsigned g_slot[STRIDE * N_NODES];  // in-CSR, column-major: [i*N + v] = src | combo<<17
__device__ float    g_S[N_NODES];              // aggr after hop 1
__device__ float    g_A2[N_NODES];             // aggr after hop 2
__device__ float    g_A3[N_NODES];             // aggr after hop 3

// Monotonic (replay-safe) grid barrier. Never reset. Shared by both kernels
// (monotonic tickets make cross-kernel reuse safe).
__device__ unsigned g_arrive = 0;
__device__ volatile unsigned g_release = 0;

__device__ __forceinline__ void grid_barrier(unsigned nb) {
    __syncthreads();
    if (threadIdx.x == 0) {
        __threadfence();
        unsigned ticket = atomicAdd(&g_arrive, 1u);
        unsigned target = ticket - (ticket % nb) + nb;
        if (ticket % nb == nb - 1u) {
            g_release = target;
        } else {
            while (*(volatile unsigned*)&g_release < target) { }
        }
        __threadfence();
    }
    __syncthreads();
}

__device__ __forceinline__ int ntp_lookup(int id) {
    return (int)((__ldg(&g_ntp[id >> 4]) >> ((id & 15) << 1)) & 3u);
}

// ---------------------------------------------------------------------------
// K_A (persistent, NATURAL register count — no launch bounds, so the build
// phase never spills): init phase, grid barrier, build phase.
// ---------------------------------------------------------------------------
__global__ void kA_init_build(
    const int* __restrict__ src, const int* __restrict__ dst,
    const int* __restrict__ etyp, const int* __restrict__ ntyp,
    const float* __restrict__ W1, const float* __restrict__ b1,
    const float* __restrict__ W2, const float* __restrict__ b2,
    unsigned NB, int NT) {
    int gt = blockIdx.x * blockDim.x + threadIdx.x;

    // ---- phase 0: LUT (32 lanes/combo) + pack node types + zero cursors ----
    if (gt < NUM_COMBOS * 32) {
        int combo = gt >> 5, lane = gt & 31;
        int et = combo >> 4, ht = (combo >> 2) & 3, tt = combo & 3;
        float acc = 0.f;
#pragma unroll
        for (int j = 0; j < 2; j++) {
            int k = lane + j * 32;
            float h = W1[et * HIDDEN + k]
                    + W1[(NUM_EDGE_TYPES + ht) * HIDDEN + k]
                    + W1[(NUM_EDGE_TYPES + NUM_NODE_TYPES + tt) * HIDDEN + k]
                    + b1[k];
            float h3 = h * h * h;        // jax.nn.gelu default (tanh approximation)
            float g = 0.5f * h * (1.f + tanhf(0.7978845608028654f * (h + 0.044715f * h3)));
            acc = fmaf(g, W2[k], acc);
        }
#pragma unroll
        for (int o = 16; o > 0; o >>= 1) acc += __shfl_xor_sync(0xffffffffu, acc, o);
        if (lane == 0) g_lut[combo] = 1.f / (1.f + expf(-(acc + b2[0])));
    }

    for (int w = gt; w < NTP_WORDS; w += NT) {
        const int* nt4 = ntyp + (w << 4);
        unsigned p = 0;
#pragma unroll
        for (int j = 0; j < 4; j++) {
            int4 q = *reinterpret_cast<const int4*>(nt4 + j * 4);
            p |= (unsigned)(q.x & 3) << ((j * 4 + 0) << 1);
            p |= (unsigned)(q.y & 3) << ((j * 4 + 1) << 1);
            p |= (unsigned)(q.z & 3) << ((j * 4 + 2) << 1);
            p |= (unsigned)(q.w & 3) << ((j * 4 + 3) << 1);
        }
        g_ntp[w] = p;
    }

    for (int v = gt; v < N_NODES; v += NT) g_cnt[v] = 0;
    grid_barrier(NB);

    // ---- phase 1: build packed in-CSR (2 random ops/edge) ----
    for (int i = gt * 4; i < N_EDGES; i += NT * 4) {
        int4 s = *reinterpret_cast<const int4*>(src + i);
        int4 d = *reinterpret_cast<const int4*>(dst + i);
        int4 t = *reinterpret_cast<const int4*>(etyp + i);

        unsigned c0 = (unsigned)((t.x << 4) + (ntp_lookup(s.x) << 2) + ntp_lookup(d.x));
        unsigned c1 = (unsigned)((t.y << 4) + (ntp_lookup(s.y) << 2) + ntp_lookup(d.y));
        unsigned c2 = (unsigned)((t.z << 4) + (ntp_lookup(s.z) << 2) + ntp_lookup(d.z));
        unsigned c3 = (unsigned)((t.w << 4) + (ntp_lookup(s.w) << 2) + ntp_lookup(d.w));

        int p0 = atomicAdd(&g_cnt[d.x], 1);
        int p1 = atomicAdd(&g_cnt[d.y], 1);
        int p2 = atomicAdd(&g_cnt[d.z], 1);
        int p3 = atomicAdd(&g_cnt[d.w], 1);

        if (p0 < STRIDE) g_slot[p0 * N_NODES + d.x] = (unsigned)s.x | (c0 << 17);
        if (p1 < STRIDE) g_slot[p1 * N_NODES + d.y] = (unsigned)s.y | (c1 << 17);
        if (p2 < STRIDE) g_slot[p2 * N_NODES + d.z] = (unsigned)s.z | (c2 << 17);
        if (p3 < STRIDE) g_slot[p3 * N_NODES + d.w] = (unsigned)s.w | (c3 << 17);
    }
}

// ---------------------------------------------------------------------------
// Hop gather, 4 threads/node (phases 0..3), MLP-2 inner loop.
//   out[v] = S[v] + sum_{in-edges e of v} in[src_e]
// LIMP padded to a multiple of NT: uniform trips -> full-mask shuffles legal.
// ---------------------------------------------------------------------------
__device__ __forceinline__ void hop4(const float* __restrict__ in,
                                     float* __restrict__ out,
                                     int gt, int NT, int LIMP) {
    for (int t = gt; t < LIMP; t += NT) {
        int v = t >> 2, ph = t & 3;
        float a0 = 0.f, a1 = 0.f;
        if (v < N_NODES) {
            int c = min(g_cnt[v], STRIDE);
            int i = ph;
            for (; i + 4 < c; i += 8) {
                unsigned s0 = g_slot[(i    ) * N_NODES + v];
                unsigned s1 = g_slot[(i + 4) * N_NODES + v];
                a0 += __ldg(in + (s0 & SRC_MASK));
                a1 += __ldg(in + (s1 & SRC_MASK));
            }
            if (i < c) a0 += __ldg(in + (g_slot[i * N_NODES + v] & SRC_MASK));
        }
        float sum = a0 + a1;
        sum += __shfl_xor_sync(0xffffffffu, sum, 1);
        sum += __shfl_xor_sync(0xffffffffu, sum, 2);
        if (ph == 0 && v < N_NODES) out[v] = g_S[v] + sum;
    }
}

// ---------------------------------------------------------------------------
// K_B (persistent, 32-reg-friendly phases only): S-pass + 3 gather hops.
// ---------------------------------------------------------------------------
__global__ void __launch_bounds__(256, 8) kB_main(float* __restrict__ out,
                                                  unsigned NB, int NT, int LIMP) {
    __shared__ float lut_s[NUM_COMBOS];
    for (int k = threadIdx.x; k < NUM_COMBOS; k += 256) lut_s[k] = g_lut[k];
    __syncthreads();

    int gt = blockIdx.x * 256 + threadIdx.x;

    // ---- S-pass: S[v] = sum of lut[combo] over in-edges (aggr after hop 1) ----
    for (int t = gt; t < LIMP; t += NT) {
        int v = t >> 2, ph = t & 3;
        float a0 = 0.f, a1 = 0.f;
        if (v < N_NODES) {
            int c = min(g_cnt[v], STRIDE);
            int i = ph;
            for (; i + 4 < c; i += 8) {
                unsigned s0 = g_slot[(i    ) * N_NODES + v];
                unsigned s1 = g_slot[(i + 4) * N_NODES + v];
                a0 += lut_s[s0 >> 17];
                a1 += lut_s[s1 >> 17];
            }
            if (i < c) a0 += lut_s[g_slot[i * N_NODES + v] >> 17];
        }
        float sum = a0 + a1;
        sum += __shfl_xor_sync(0xffffffffu, sum, 1);
        sum += __shfl_xor_sync(0xffffffffu, sum, 2);
        if (ph == 0 && v < N_NODES) g_S[v] = sum;
    }
    grid_barrier(NB);

    hop4(g_S, g_A2, gt, NT, LIMP);    // hop 2
    grid_barrier(NB);
    hop4(g_A2, g_A3, gt, NT, LIMP);   // hop 3
    grid_barrier(NB);
    hop4(g_A3, out, gt, NT, LIMP);    // hop 4 -> d_out
}

extern "C" void kernel_launch(void* const* d_in, const int* in_sizes, int n_in,
                              void* d_out, int out_size) {
    const int* edge_index = (const int*)d_in[0];   // [2, E]
    const int* edge_type  = (const int*)d_in[1];   // [E]
    const int* node_type  = (const int*)d_in[2];   // [N]
    const float* W1 = (const float*)d_in[3];
    const float* b1 = (const float*)d_in[4];
    const float* W2 = (const float*)d_in[5];
    const float* b2 = (const float*)d_in[6];
    float* out = (float*)d_out;                    // [N, 1]

    const int* src = edge_index;
    const int* dst = edge_index + N_EDGES;

    int dev = 0, sm = 148;
    cudaGetDevice(&dev);
    cudaDeviceGetAttribute(&sm, cudaDevAttrMultiProcessorCount, dev);

    const int TB = 256;

    // K_A grid: residency-safe at K_A's NATURAL occupancy.
    int occA = 0;
    cudaOccupancyMaxActiveBlocksPerMultiprocessor(&occA, kA_init_build, TB, 0);
    if (occA < 1) occA = 1;
    if (occA > 8) occA = 8;
    unsigned NBa = (unsigned)(sm * occA);
    int NTa = (int)NBa * TB;

    // K_B grid: residency-safe at K_B's occupancy (launch_bounds(256,8)).
    int occB = 0;
    cudaOccupancyMaxActiveBlocksPerMultiprocessor(&occB, kB_main, TB, 0);
    if (occB < 1) occB = 1;
    if (occB > 8) occB = 8;
    unsigned NBb = (unsigned)(sm * occB);
    int NTb = (int)NBb * TB;
    int LIMP = ((4 * N_NODES + NTb - 1) / NTb) * NTb;  // padded: uniform warp trips

    kA_init_build<<<NBa, TB>>>(src, dst, edge_type, node_type,
                               W1, b1, W2, b2, NBa, NTa);
    kB_main<<<NBb, TB>>>(out, NBb, NTb, LIMP);
}

// round 16
// speedup vs baseline: 1.5000x; 1.0274x over previous
#include <cuda_runtime.h>

#define NUM_EDGE_TYPES 38
#define NUM_NODE_TYPES 4
#define HIDDEN 64
#define N_NODES 100000
#define N_EDGES 1600000
#define NUM_COMBOS (NUM_EDGE_TYPES * NUM_NODE_TYPES * NUM_NODE_TYPES)  // 608
#define STRIDE 64                 // in-degree cap; Poisson(16) tail @64 ~ 1e-19
#define NTP_WORDS (N_NODES / 16)  // 2-bit packed node types (25 KB, L1-resident)
#define SRC_MASK 0x1FFFF          // src < 100000 < 2^17; combo in bits [17,27)

// Scratch (device globals — no allocation allowed).
__device__ float    g_lut[NUM_COMBOS];
__device__ unsigned g_ntp[NTP_WORDS];
__device__ int      g_cnt[N_NODES];
__device__ unsigned g_slot[STRIDE * N_NODES];  // in-CSR, column-major: [i*N + v] = src | combo<<17
__device__ float    g_S[N_NODES];              // aggr after hop 1
__device__ float    g_A2[N_NODES];             // aggr after hop 2
__device__ float    g_A3[N_NODES];             // aggr after hop 3

// Monotonic (replay-safe) grid barrier. Never reset.
__device__ unsigned g_arrive = 0;
__device__ volatile unsigned g_release = 0;

__device__ __forceinline__ void grid_barrier(unsigned nb) {
    __syncthreads();
    if (threadIdx.x == 0) {
        __threadfence();
        unsigned ticket = atomicAdd(&g_arrive, 1u);
        unsigned target = ticket - (ticket % nb) + nb;
        if (ticket % nb == nb - 1u) {
            g_release = target;
        } else {
            while (*(volatile unsigned*)&g_release < target) { }
        }
        __threadfence();
    }
    __syncthreads();
}

__device__ __forceinline__ int ntp_lookup(int id) {
    return (int)((__ldg(&g_ntp[id >> 4]) >> ((id & 15) << 1)) & 3u);
}

// ---------------------------------------------------------------------------
// K1: LUT + pack node types + zero cursors. Standalone (launch-dominated).
// ---------------------------------------------------------------------------
__global__ void k_init(const float* __restrict__ W1, const float* __restrict__ b1,
                       const float* __restrict__ W2, const float* __restrict__ b2,
                       const int* __restrict__ ntyp) {
    int gt = blockIdx.x * blockDim.x + threadIdx.x;
    int NT = gridDim.x * blockDim.x;

    if (gt < NUM_COMBOS * 32) {          // 32 lanes per combo, shuffle reduce
        int combo = gt >> 5, lane = gt & 31;
        int et = combo >> 4, ht = (combo >> 2) & 3, tt = combo & 3;
        float acc = 0.f;
#pragma unroll
        for (int j = 0; j < 2; j++) {
            int k = lane + j * 32;
            float h = W1[et * HIDDEN + k]
                    + W1[(NUM_EDGE_TYPES + ht) * HIDDEN + k]
                    + W1[(NUM_EDGE_TYPES + NUM_NODE_TYPES + tt) * HIDDEN + k]
                    + b1[k];
            float h3 = h * h * h;        // jax.nn.gelu default (tanh approximation)
            float g = 0.5f * h * (1.f + tanhf(0.7978845608028654f * (h + 0.044715f * h3)));
            acc = fmaf(g, W2[k], acc);
        }
#pragma unroll
        for (int o = 16; o > 0; o >>= 1) acc += __shfl_xor_sync(0xffffffffu, acc, o);
        if (lane == 0) g_lut[combo] = 1.f / (1.f + expf(-(acc + b2[0])));
    }

    for (int w = gt; w < NTP_WORDS; w += NT) {
        const int* nt4 = ntyp + (w << 4);
        unsigned p = 0;
#pragma unroll
        for (int j = 0; j < 4; j++) {
            int4 q = *reinterpret_cast<const int4*>(nt4 + j * 4);
            p |= (unsigned)(q.x & 3) << ((j * 4 + 0) << 1);
            p |= (unsigned)(q.y & 3) << ((j * 4 + 1) << 1);
            p |= (unsigned)(q.z & 3) << ((j * 4 + 2) << 1);
            p |= (unsigned)(q.w & 3) << ((j * 4 + 3) << 1);
        }
        g_ntp[w] = p;
    }

    for (int v = gt; v < N_NODES; v += NT) g_cnt[v] = 0;
}

// ---------------------------------------------------------------------------
// K2: build packed in-CSR. Free-running wide grid, NATURAL register count.
//     2 random ops/edge: cursor ATOMG + scattered 4B slot store.
// ---------------------------------------------------------------------------
__global__ void k_build(const int* __restrict__ src, const int* __restrict__ dst,
                        const int* __restrict__ etyp) {
    int i = (blockIdx.x * blockDim.x + threadIdx.x) * 4;
    if (i >= N_EDGES) return;

    int4 s = *reinterpret_cast<const int4*>(src + i);
    int4 d = *reinterpret_cast<const int4*>(dst + i);
    int4 t = *reinterpret_cast<const int4*>(etyp + i);

    unsigned c0 = (unsigned)((t.x << 4) + (ntp_lookup(s.x) << 2) + ntp_lookup(d.x));
    unsigned c1 = (unsigned)((t.y << 4) + (ntp_lookup(s.y) << 2) + ntp_lookup(d.y));
    unsigned c2 = (unsigned)((t.z << 4) + (ntp_lookup(s.z) << 2) + ntp_lookup(d.z));
    unsigned c3 = (unsigned)((t.w << 4) + (ntp_lookup(s.w) << 2) + ntp_lookup(d.w));

    int p0 = atomicAdd(&g_cnt[d.x], 1);
    int p1 = atomicAdd(&g_cnt[d.y], 1);
    int p2 = atomicAdd(&g_cnt[d.z], 1);
    int p3 = atomicAdd(&g_cnt[d.w], 1);

    if (p0 < STRIDE) g_slot[p0 * N_NODES + d.x] = (unsigned)s.x | (c0 << 17);
    if (p1 < STRIDE) g_slot[p1 * N_NODES + d.y] = (unsigned)s.y | (c1 << 17);
    if (p2 < STRIDE) g_slot[p2 * N_NODES + d.z] = (unsigned)s.z | (c2 << 17);
    if (p3 < STRIDE) g_slot[p3 * N_NODES + d.w] = (unsigned)s.w | (c3 << 17);
}

// ---------------------------------------------------------------------------
// Hop gather, 4 threads/node (phases 0..3), MLP-2 inner loop.
//   out[v] = S[v] + sum_{in-edges e of v} in[src_e]
// LIMP padded to a multiple of NT: uniform trips -> full-mask shuffles legal.
// ---------------------------------------------------------------------------
__device__ __forceinline__ void hop4(const float* __restrict__ in,
                                     float* __restrict__ out,
                                     int gt, int NT, int LIMP) {
    for (int t = gt; t < LIMP; t += NT) {
        int v = t >> 2, ph = t & 3;
        float a0 = 0.f, a1 = 0.f;
        if (v < N_NODES) {
            int c = min(g_cnt[v], STRIDE);
            int i = ph;
            for (; i + 4 < c; i += 8) {
                unsigned s0 = g_slot[(i    ) * N_NODES + v];
                unsigned s1 = g_slot[(i + 4) * N_NODES + v];
                a0 += __ldg(in + (s0 & SRC_MASK));
                a1 += __ldg(in + (s1 & SRC_MASK));
            }
            if (i < c) a0 += __ldg(in + (g_slot[i * N_NODES + v] & SRC_MASK));
        }
        float sum = a0 + a1;
        sum += __shfl_xor_sync(0xffffffffu, sum, 1);
        sum += __shfl_xor_sync(0xffffffffu, sum, 2);
        if (ph == 0 && v < N_NODES) out[v] = g_S[v] + sum;
    }
}

// ---------------------------------------------------------------------------
// K3 (persistent, launch_bounds(256,8) -> 21 regs, occ ~97%, measured 41.4us):
// S-pass + 3 gather hops with grid barriers.
// ---------------------------------------------------------------------------
__global__ void __launch_bounds__(256, 8) kB_main(float* __restrict__ out,
                                                  unsigned NB, int NT, int LIMP) {
    __shared__ float lut_s[NUM_COMBOS];
    for (int k = threadIdx.x; k < NUM_COMBOS; k += 256) lut_s[k] = g_lut[k];
    __syncthreads();

    int gt = blockIdx.x * 256 + threadIdx.x;

    // ---- S-pass: S[v] = sum of lut[combo] over in-edges (aggr after hop 1) ----
    for (int t = gt; t < LIMP; t += NT) {
        int v = t >> 2, ph = t & 3;
        float a0 = 0.f, a1 = 0.f;
        if (v < N_NODES) {
            int c = min(g_cnt[v], STRIDE);
            int i = ph;
            for (; i + 4 < c; i += 8) {
                unsigned s0 = g_slot[(i    ) * N_NODES + v];
                unsigned s1 = g_slot[(i + 4) * N_NODES + v];
                a0 += lut_s[s0 >> 17];
                a1 += lut_s[s1 >> 17];
            }
            if (i < c) a0 += lut_s[g_slot[i * N_NODES + v] >> 17];
        }
        float sum = a0 + a1;
        sum += __shfl_xor_sync(0xffffffffu, sum, 1);
        sum += __shfl_xor_sync(0xffffffffu, sum, 2);
        if (ph == 0 && v < N_NODES) g_S[v] = sum;
    }
    grid_barrier(NB);

    hop4(g_S, g_A2, gt, NT, LIMP);    // hop 2
    grid_barrier(NB);
    hop4(g_A2, g_A3, gt, NT, LIMP);   // hop 3
    grid_barrier(NB);
    hop4(g_A3, out, gt, NT, LIMP);    // hop 4 -> d_out
}

extern "C" void kernel_launch(void* const* d_in, const int* in_sizes, int n_in,
                              void* d_out, int out_size) {
    const int* edge_index = (const int*)d_in[0];   // [2, E]
    const int* edge_type  = (const int*)d_in[1];   // [E]
    const int* node_type  = (const int*)d_in[2];   // [N]
    const float* W1 = (const float*)d_in[3];
    const float* b1 = (const float*)d_in[4];
    const float* W2 = (const float*)d_in[5];
    const float* b2 = (const float*)d_in[6];
    float* out = (float*)d_out;                    // [N, 1]

    const int* src = edge_index;
    const int* dst = edge_index + N_EDGES;

    int dev = 0, sm = 148;
    cudaGetDevice(&dev);
    cudaDeviceGetAttribute(&sm, cudaDevAttrMultiProcessorCount, dev);

    const int TB = 256;
    const int initBlocks = 256;
    const int buildBlocks = (N_EDGES / 4 + TB - 1) / TB;  // 1563, free-running

    int occB = 0;
    cudaOccupancyMaxActiveBlocksPerMultiprocessor(&occB, kB_main, TB, 0);
    if (occB < 1) occB = 1;
    if (occB > 8) occB = 8;
    unsigned NBb = (unsigned)(sm * occB);
    int NTb = (int)NBb * TB;
    int LIMP = ((4 * N_NODES + NTb - 1) / NTb) * NTb;  // padded: uniform warp trips

    k_init<<<initBlocks, TB>>>(W1, b1, W2, b2, node_type);
    k_build<<<buildBlocks, TB>>>(src, dst, edge_type);
    kB_main<<<NBb, TB>>>(out, NBb, NTb, LIMP);
}